// round 12
// baseline (speedup 1.0000x reference)
#include <cuda_runtime.h>
#include <cuda_fp16.h>
#include <math.h>
#include <stdint.h>

#define NB 8
#define SEQ 512
#define MAXSEQ 4096
#define DIM 512
#define INTER 1024
#define NLAYERS 4
#define P1 516
#define M1 (NB*P1)            // 4128 gemm1 rows (packed)
#define M1T 33                // ceil(4128/128)
#define CONST_W 3581.0f

// ---------------- scratch ----------------
__device__ float  g_x   [NB*SEQ*DIM];
__device__ __half g_a1  [(M1T*128)*DIM];      // activations fp16 (rows >= 4128 stay zero)
__device__ __half g_a2  [NB*SEQ*INTER];
__device__ __half g_w1  [NLAYERS*INTER*DIM];  // pw1_w transposed [N][K], fp16
__device__ __half g_w2  [NLAYERS*DIM*INTER];  // pw2_w transposed [N][K], fp16
__device__ float  g_sumsq[NB*INTER];
__device__ float  g_alpha[NB*INTER];
__device__ int    g_needfix[NB];

// ---------------- helpers ----------------
__device__ __forceinline__ uint32_t smem_u32(const void* p) {
    uint32_t a;
    asm("{ .reg .u64 t; cvta.to.shared.u64 t, %1; cvt.u32.u64 %0, t; }" : "=r"(a) : "l"(p));
    return a;
}

#define STAGE_BYTES 49152u      // A 16KB + B 32KB
#define NSTAGE 3

// ---------------- compute one 64-K stage: warp tile 64x64 (8 warps, 2Mx4N) ----------------
__device__ __forceinline__ void compute_stage(uint32_t sbs,
                                              const uint32_t aoff[4], const uint32_t boff[4],
                                              float acc[4][8][4]) {
    #pragma unroll
    for (int ks = 0; ks < 4; ks++) {
        uint32_t kx = (uint32_t)ks * 32u;
        uint32_t a_frag[4][4];
        #pragma unroll
        for (int i = 0; i < 4; i++)
            asm volatile("ldmatrix.sync.aligned.m8n8.x4.shared.b16 {%0,%1,%2,%3}, [%4];"
                : "=r"(a_frag[i][0]), "=r"(a_frag[i][1]), "=r"(a_frag[i][2]), "=r"(a_frag[i][3])
                : "r"((sbs + aoff[i]) ^ kx));
        uint32_t b_frag[8][2];
        #pragma unroll
        for (int jj = 0; jj < 4; jj++) {
            uint32_t r0, r1, r2, r3;
            asm volatile("ldmatrix.sync.aligned.m8n8.x4.shared.b16 {%0,%1,%2,%3}, [%4];"
                : "=r"(r0), "=r"(r1), "=r"(r2), "=r"(r3) : "r"((sbs + boff[jj]) ^ kx));
            b_frag[jj*2+0][0] = r0; b_frag[jj*2+0][1] = r2;
            b_frag[jj*2+1][0] = r1; b_frag[jj*2+1][1] = r3;
        }
        #pragma unroll
        for (int i = 0; i < 4; i++)
            #pragma unroll
            for (int j = 0; j < 8; j++)
                asm volatile(
                    "mma.sync.aligned.m16n8k16.row.col.f32.f16.f16.f32 "
                    "{%0,%1,%2,%3}, {%4,%5,%6,%7}, {%8,%9}, {%0,%1,%2,%3};"
                    : "+f"(acc[i][j][0]), "+f"(acc[i][j][1]),
                      "+f"(acc[i][j][2]), "+f"(acc[i][j][3])
                    : "r"(a_frag[i][0]), "r"(a_frag[i][1]),
                      "r"(a_frag[i][2]), "r"(a_frag[i][3]),
                      "r"(b_frag[j][0]), "r"(b_frag[j][1]));
    }
}

// ---------------- mainloop over chunk range [c0, c1): A 128 rows, B 256 rows ----------------
__device__ __forceinline__ void mma_mainloop(
    const __half* A, const __half* B, int K, int c0, int c1, int m0, int n0,
    uint32_t smem_base, int t, int warpM, int warpN, int lane,
    float acc[4][8][4]) {
    int lrow = t >> 3, lkg = t & 7;        // 256 threads -> 32 rows x 8 groups per pass
    uint32_t so = (uint32_t)lrow * 128u + (((uint32_t)lkg * 16u) ^ (((uint32_t)lrow & 7u) * 16u));
    size_t srcoff = (size_t)lrow * K + lkg * 8;
    size_t rbytes = (size_t)32 * K * 2;    // 32 rows per pass

    const __half* pA = A + (size_t)m0 * K + srcoff + (size_t)c0 * 64;
    const __half* pB = B + (size_t)n0 * K + srcoff + (size_t)c0 * 64;

    int la = lane & 15, lh = lane >> 4;
    uint32_t aoff[4], boff[4];
    #pragma unroll
    for (int i = 0; i < 4; i++) {
        uint32_t row = (uint32_t)(warpM * 64 + i * 16 + la);
        aoff[i] = row * 128u + (((uint32_t)lh * 16u) ^ ((row & 7u) * 16u));
    }
    #pragma unroll
    for (int jj = 0; jj < 4; jj++) {
        uint32_t row = (uint32_t)(warpN * 64 + jj * 16 + la);
        boff[jj] = 16384u + row * 128u + (((uint32_t)lh * 16u) ^ ((row & 7u) * 16u));
    }

#define ISSUE(slot) do { \
    uint32_t dst = smem_base + (uint32_t)(slot) * STAGE_BYTES; \
    const char* sa = (const char*)pA; \
    _Pragma("unroll") \
    for (int ii = 0; ii < 4; ii++) { \
        asm volatile("cp.async.cg.shared.global [%0], [%1], 16;" \
                     :: "r"(dst + so + (uint32_t)ii * 4096u), "l"(sa)); \
        sa += rbytes; } \
    const char* sb = (const char*)pB; \
    _Pragma("unroll") \
    for (int ii = 0; ii < 8; ii++) { \
        asm volatile("cp.async.cg.shared.global [%0], [%1], 16;" \
                     :: "r"(dst + 16384u + so + (uint32_t)ii * 4096u), "l"(sb)); \
        sb += rbytes; } \
    pA += 64; pB += 64; } while(0)

    ISSUE(0); asm volatile("cp.async.commit_group;" ::: "memory");
    ISSUE(1); asm volatile("cp.async.commit_group;" ::: "memory");
    int stage = 0, pf_slot = 2;
    for (int kc = c0; kc < c1; kc++) {
        asm volatile("cp.async.wait_group 1;" ::: "memory");
        __syncthreads();
        if (kc + 2 < c1) {
            ISSUE(pf_slot);
            pf_slot = (pf_slot + 1 == NSTAGE) ? 0 : pf_slot + 1;
        }
        asm volatile("cp.async.commit_group;" ::: "memory");
        compute_stage(smem_base + (uint32_t)stage * STAGE_BYTES, aoff, boff, acc);
        stage = (stage + 1 == NSTAGE) ? 0 : stage + 1;
    }
#undef ISSUE
}

__device__ __forceinline__ float gelu_exact(float v) {
    return 0.5f * v * (1.0f + erff(v * 0.7071067811865476f));
}

// ---------------- GEMM1: h = gelu(A1 @ W1t^T + b); writes fp16 h; GRN sumsq ----------------
__global__ void __launch_bounds__(256, 1) gemm1_mma(int l, const float* __restrict__ bias) {
    extern __shared__ char smem[];
    uint32_t sbase = smem_u32(smem);
    int t = threadIdx.x, lane = t & 31, wid = t >> 5;
    int warpM = wid & 1, warpN = wid >> 1;           // 2M x 4N warps, 64x64 tiles
    int n0 = blockIdx.x * 256, m0 = blockIdx.y * 128;
    float acc[4][8][4] = {};
    mma_mainloop(g_a1, g_w1 + (size_t)l * INTER * DIM,
                 DIM, 0, 8, m0, n0, sbase, t, warpM, warpN, lane, acc);
    int b_lo = m0 / P1;
    int boundary = (b_lo + 1) * P1;
    float cs[2][8][2] = {};
    #pragma unroll
    for (int i = 0; i < 4; i++) {
        #pragma unroll
        for (int half = 0; half < 2; half++) {
            int r = m0 + warpM * 64 + i * 16 + (lane >> 2) + 8 * half;
            int bs = (r >= boundary) ? 1 : 0;
            int p = r - (bs ? boundary : b_lo * P1);
            int b = b_lo + bs;
            float wgt = (r >= M1) ? 0.0f :
                        ((p < 515) ? 1.0f : ((p == 515) ? CONST_W : 0.0f));
            bool wr_a2 = (r < M1) && (p < 512);
            size_t row2 = (size_t)(b * SEQ + p) * INTER;
            #pragma unroll
            for (int j = 0; j < 8; j++) {
                int n = n0 + warpN * 64 + j * 8 + (lane & 3) * 2;
                float g0 = gelu_exact(acc[i][j][half*2+0] + bias[n]);
                float g1 = gelu_exact(acc[i][j][half*2+1] + bias[n+1]);
                cs[bs][j][0] += wgt * g0 * g0;
                cs[bs][j][1] += wgt * g1 * g1;
                if (wr_a2) {
                    // GRN fast path: alpha==1, grn_b==0 -> A2 = h (fixup_kernel repairs otherwise)
                    *(__half2*)&g_a2[row2 + n] =
                        __half2(__float2half_rn(g0), __float2half_rn(g1));
                }
            }
        }
    }
    #pragma unroll
    for (int bs = 0; bs < 2; bs++)
        #pragma unroll
        for (int j = 0; j < 8; j++)
            #pragma unroll
            for (int s = 0; s < 2; s++) {
                float v = cs[bs][j][s];
                v += __shfl_xor_sync(0xffffffffu, v, 4);
                v += __shfl_xor_sync(0xffffffffu, v, 8);
                v += __shfl_xor_sync(0xffffffffu, v, 16);
                cs[bs][j][s] = v;
            }
    if (lane < 4) {
        #pragma unroll
        for (int j = 0; j < 8; j++) {
            int n = n0 + warpN * 64 + j * 8 + lane * 2;
            atomicAdd(&g_sumsq[b_lo * INTER + n],     cs[0][j][0]);
            atomicAdd(&g_sumsq[b_lo * INTER + n + 1], cs[0][j][1]);
            if (b_lo + 1 < NB) {
                atomicAdd(&g_sumsq[(b_lo + 1) * INTER + n],     cs[1][j][0]);
                atomicAdd(&g_sumsq[(b_lo + 1) * INTER + n + 1], cs[1][j][1]);
            }
        }
    }
}

// ---------------- GEMM2: x += A2 @ W2t^T + b  (K-split 2, atomic epilogue) ----------------
__global__ void __launch_bounds__(256, 1) gemm2_mma(int l, const float* __restrict__ bias) {
    extern __shared__ char smem[];
    uint32_t sbase = smem_u32(smem);
    int t = threadIdx.x, lane = t & 31, wid = t >> 5;
    int warpM = wid & 1, warpN = wid >> 1;
    int n0 = blockIdx.x * 256, m0 = blockIdx.y * 128;
    int split = blockIdx.z;
    float acc[4][8][4] = {};
    mma_mainloop(g_a2, g_w2 + (size_t)l * DIM * INTER,
                 INTER, split * 8, split * 8 + 8, m0, n0,
                 sbase, t, warpM, warpN, lane, acc);
    #pragma unroll
    for (int i = 0; i < 4; i++) {
        int rowbase = m0 + warpM * 64 + i * 16 + (lane >> 2);
        #pragma unroll
        for (int half = 0; half < 2; half++) {
            int m = rowbase + 8 * half;
            #pragma unroll
            for (int j = 0; j < 8; j++) {
                int n = n0 + warpN * 64 + j * 8 + (lane & 3) * 2;
                size_t xo = (size_t)m * DIM + n;
                float add0 = acc[i][j][half*2+0];
                float add1 = acc[i][j][half*2+1];
                if (split == 0) { add0 += bias[n]; add1 += bias[n+1]; }
                atomicAdd(&g_x[xo],     add0);
                atomicAdd(&g_x[xo + 1], add1);
            }
        }
    }
}

// ---------------- embed + abs pos enc (paired sincos) ----------------
__global__ void embed_kernel(const int* __restrict__ text, const float* __restrict__ emb) {
    int bp = blockIdx.x;
    int p = bp & 511, b = bp >> 9;
    int tok = text[b * SEQ + p] + 1;
    const float* erow = emb + (size_t)tok * DIM;
    float* orow = g_x + (size_t)bp * DIM;
    int i = threadIdx.x;
    float f   = expf(-9.210340371976184f * (float)i / 256.0f);
    float ang = (float)p * f;
    float sv, cv;
    sincosf(ang, &sv, &cv);
    orow[i]       = erow[i]       + cv;
    orow[i + 256] = erow[i + 256] + sv;
}

// ---------------- dwconv(k=7) + LayerNorm -> fp16 (packed rows) ----------------
__global__ void convln_kernel(const float* __restrict__ dw_w, const float* __restrict__ dw_b,
                              const float* __restrict__ ln_g, const float* __restrict__ ln_b) {
    int bp = blockIdx.x;
    int b = bp / P1;
    int p = bp - b * P1;
    int t = threadIdx.x;
    float y[4];
    #pragma unroll
    for (int j = 0; j < 4; j++) {
        int c = t + j * 128;
        float acc = dw_b[c];
        #pragma unroll
        for (int k = 0; k < 7; k++) {
            int pp = p - 3 + k;
            if (pp >= 0 && pp < SEQ)
                acc += dw_w[k * DIM + c] * g_x[(size_t)(b * SEQ + pp) * DIM + c];
        }
        y[j] = acc;
    }
    float s = y[0]+y[1]+y[2]+y[3];
    float s2 = y[0]*y[0]+y[1]*y[1]+y[2]*y[2]+y[3]*y[3];
    #pragma unroll
    for (int off = 16; off; off >>= 1) {
        s  += __shfl_xor_sync(0xffffffffu, s,  off);
        s2 += __shfl_xor_sync(0xffffffffu, s2, off);
    }
    __shared__ float sh[8];
    int w = t >> 5;
    if ((t & 31) == 0) { sh[w] = s; sh[4 + w] = s2; }
    __syncthreads();
    float S  = sh[0]+sh[1]+sh[2]+sh[3];
    float S2 = sh[4]+sh[5]+sh[6]+sh[7];
    float mean = S * (1.0f/512.0f);
    float var  = S2 * (1.0f/512.0f) - mean * mean;
    float inv  = rsqrtf(var + 1e-6f);
    size_t base = (size_t)bp * DIM;
    #pragma unroll
    for (int j = 0; j < 4; j++) {
        int c = t + j * 128;
        float v = (y[j] - mean) * inv * ln_g[c] + ln_b[c];
        g_a1[base + c] = __float2half_rn(v);
    }
}

// ---------------- GRN finalize: alpha + per-batch needfix flag; resets sumsq ----------------
__global__ void alpha_kernel(const float* __restrict__ grn_g, const float* __restrict__ grn_b) {
    int b = blockIdx.x;
    int i = threadIdx.x;
    float gx = sqrtf(g_sumsq[b * INTER + i]);
    g_sumsq[b * INTER + i] = 0.0f;
    float r = gx;
    #pragma unroll
    for (int off = 16; off; off >>= 1) r += __shfl_xor_sync(0xffffffffu, r, off);
    __shared__ float sh[32];
    __shared__ float meansh;
    if ((i & 31) == 0) sh[i >> 5] = r;
    __syncthreads();
    if (i < 32) {
        float v = sh[i];
        #pragma unroll
        for (int off = 16; off; off >>= 1) v += __shfl_xor_sync(0xffffffffu, v, off);
        if (i == 0) meansh = v * (1.0f/1024.0f);
    }
    __syncthreads();
    float nx = gx / (meansh + 1e-6f);
    float alpha = grn_g[i] * nx + 1.0f;
    g_alpha[b * INTER + i] = alpha;
    int bad = (alpha != 1.0f) || (grn_b[i] != 0.0f);
    int any = __syncthreads_or(bad);
    if (i == 0) g_needfix[b] = any;
}

// ---------------- fixup: only if GRN non-trivial — rewrite A2 in place ----------------
__global__ void fixup_kernel(const float* __restrict__ grn_b) {
    int row = blockIdx.x;             // b*512 + p
    int b = row >> 9;
    if (!g_needfix[b]) return;
    const float* al = g_alpha + b * INTER;
    __half* oh = g_a2 + (size_t)row * INTER;
    int i = threadIdx.x * 2;          // 512 threads x 2
    __half2 hh = *(__half2*)&oh[i];
    float v0 = al[i]     * __half2float(hh.x) + grn_b[i];
    float v1 = al[i + 1] * __half2float(hh.y) + grn_b[i + 1];
    *(__half2*)&oh[i] = __half2(__float2half_rn(v0), __float2half_rn(v1));
}

// ---------------- weight transpose + fp16 ----------------
__global__ void prep_w(const float* __restrict__ pw1_w, const float* __restrict__ pw2_w) {
    int which = blockIdx.z & 1;
    int l = blockIdx.z >> 1;
    const float* src; __half* dh;
    int R, C;
    if (which == 0) { src = pw1_w + (size_t)l * DIM * INTER; R = DIM;  C = INTER;
                      dh = g_w1 + (size_t)l * INTER * DIM; }
    else            { src = pw2_w + (size_t)l * INTER * DIM; R = INTER; C = DIM;
                      dh = g_w2 + (size_t)l * DIM * INTER; }
    int cx = blockIdx.x * 32, ry = blockIdx.y * 32;
    if (cx >= C || ry >= R) return;
    __shared__ float tl[32][33];
    int tx = threadIdx.x, ty = threadIdx.y;
    #pragma unroll
    for (int i = 0; i < 4; i++)
        tl[ty * 4 + i][tx] = src[(size_t)(ry + ty * 4 + i) * C + cx + tx];
    __syncthreads();
    #pragma unroll
    for (int i = 0; i < 4; i++)
        dh[(size_t)(cx + ty * 4 + i) * R + ry + tx] = __float2half_rn(tl[tx][ty * 4 + i]);
}

// ---------------- upsample ----------------
__global__ void upsample_kernel(const int* __restrict__ seq_len, float* __restrict__ out) {
    int bp = blockIdx.x;
    int b = bp >> 12, p = bp & 4095;
    int al = seq_len[b];
    float4* orow = (float4*)(out + (size_t)bp * DIM);
    if (p >= al) {
        for (int c = threadIdx.x; c < DIM / 4; c += blockDim.x)
            orow[c] = make_float4(0.f, 0.f, 0.f, 0.f);
        return;
    }
    int base  = al >> 9;
    int rem   = al & 511;
    int split = (512 - rem) * base;
    int j = (p < split) ? (p / base) : ((512 - rem) + (p - split) / (base + 1));
    if (j > 511) j = 511;
    const float4* xrow = (const float4*)(g_x + (size_t)(b * SEQ + j) * DIM);
    for (int c = threadIdx.x; c < DIM / 4; c += blockDim.x) orow[c] = xrow[c];
}

// ---------------- launch ----------------
extern "C" void kernel_launch(void* const* d_in, const int* in_sizes, int n_in,
                              void* d_out, int out_size) {
    const int*   text    = (const int*)  d_in[0];
    const int*   seq_len = (const int*)  d_in[1];
    const float* emb     = (const float*)d_in[2];
    const float* dw_w    = (const float*)d_in[3];
    const float* dw_b    = (const float*)d_in[4];
    const float* ln_g    = (const float*)d_in[5];
    const float* ln_b    = (const float*)d_in[6];
    const float* pw1_w   = (const float*)d_in[7];
    const float* pw1_b   = (const float*)d_in[8];
    const float* grn_g   = (const float*)d_in[9];
    const float* grn_b   = (const float*)d_in[10];
    const float* pw2_w   = (const float*)d_in[11];
    const float* pw2_b   = (const float*)d_in[12];
    float* out = (float*)d_out;

    static const int SMEM_BYTES = NSTAGE * (int)STAGE_BYTES;  // 144 KB
    cudaFuncSetAttribute(gemm1_mma, cudaFuncAttributeMaxDynamicSharedMemorySize, SMEM_BYTES);
    cudaFuncSetAttribute(gemm2_mma, cudaFuncAttributeMaxDynamicSharedMemorySize, SMEM_BYTES);

    prep_w<<<dim3(32, 32, 2 * NLAYERS), dim3(32, 8)>>>(pw1_w, pw2_w);
    embed_kernel<<<NB * SEQ, 256>>>(text, emb);
    for (int l = 0; l < NLAYERS; l++) {
        convln_kernel<<<NB * P1, 128>>>(dw_w + l * 7 * DIM, dw_b + l * DIM,
                                        ln_g + l * DIM, ln_b + l * DIM);
        gemm1_mma<<<dim3(INTER / 256, M1T), 256, SMEM_BYTES>>>(l, pw1_b + l * INTER);
        alpha_kernel<<<NB, 1024>>>(grn_g + l * INTER, grn_b + l * INTER);
        fixup_kernel<<<NB * SEQ, 512>>>(grn_b + l * INTER);
        gemm2_mma<<<dim3(DIM / 256, NB * SEQ / 128, 2), 256, SMEM_BYTES>>>(l, pw2_b + l * DIM);
    }
    upsample_kernel<<<NB * MAXSEQ, 128>>>(seq_len, out);
}

// round 13
// speedup vs baseline: 1.1390x; 1.1390x over previous
#include <cuda_runtime.h>
#include <cuda_fp16.h>
#include <math.h>
#include <stdint.h>

#define NB 8
#define SEQ 512
#define MAXSEQ 4096
#define DIM 512
#define INTER 1024
#define NLAYERS 4
#define P1 516
#define M1 (NB*P1)            // 4128 gemm1 rows (packed)
#define M1T 33                // ceil(4128/128)
#define CONST_W 3581.0f

// ---------------- scratch ----------------
__device__ float  g_x   [NB*SEQ*DIM];
__device__ __half g_a1  [(M1T*128)*DIM];      // activations fp16 (rows >= 4128 stay zero)
__device__ __half g_a2  [NB*SEQ*INTER];
__device__ __half g_w1  [NLAYERS*INTER*DIM];  // pw1_w transposed [N][K], fp16
__device__ __half g_w2  [NLAYERS*DIM*INTER];  // pw2_w transposed [N][K], fp16
__device__ float  g_sumsq[NB*INTER];

// ---------------- helpers ----------------
__device__ __forceinline__ uint32_t smem_u32(const void* p) {
    uint32_t a;
    asm("{ .reg .u64 t; cvta.to.shared.u64 t, %1; cvt.u32.u64 %0, t; }" : "=r"(a) : "l"(p));
    return a;
}

#define STAGE_BYTES 32768u      // A 16KB + B 16KB
#define NSTAGE 3

// ---------------- compute one 64-K stage: warp tile 64x64 (4 warps, 2x2) ----------------
__device__ __forceinline__ void compute_stage(uint32_t sbs,
                                              const uint32_t aoff[4], const uint32_t boff[4],
                                              float acc[4][8][4]) {
    #pragma unroll
    for (int ks = 0; ks < 4; ks++) {
        uint32_t kx = (uint32_t)ks * 32u;
        uint32_t a_frag[4][4];
        #pragma unroll
        for (int i = 0; i < 4; i++)
            asm volatile("ldmatrix.sync.aligned.m8n8.x4.shared.b16 {%0,%1,%2,%3}, [%4];"
                : "=r"(a_frag[i][0]), "=r"(a_frag[i][1]), "=r"(a_frag[i][2]), "=r"(a_frag[i][3])
                : "r"((sbs + aoff[i]) ^ kx));
        uint32_t b_frag[8][2];
        #pragma unroll
        for (int jj = 0; jj < 4; jj++) {
            uint32_t r0, r1, r2, r3;
            asm volatile("ldmatrix.sync.aligned.m8n8.x4.shared.b16 {%0,%1,%2,%3}, [%4];"
                : "=r"(r0), "=r"(r1), "=r"(r2), "=r"(r3) : "r"((sbs + boff[jj]) ^ kx));
            b_frag[jj*2+0][0] = r0; b_frag[jj*2+0][1] = r2;
            b_frag[jj*2+1][0] = r1; b_frag[jj*2+1][1] = r3;
        }
        #pragma unroll
        for (int i = 0; i < 4; i++)
            #pragma unroll
            for (int j = 0; j < 8; j++)
                asm volatile(
                    "mma.sync.aligned.m16n8k16.row.col.f32.f16.f16.f32 "
                    "{%0,%1,%2,%3}, {%4,%5,%6,%7}, {%8,%9}, {%0,%1,%2,%3};"
                    : "+f"(acc[i][j][0]), "+f"(acc[i][j][1]),
                      "+f"(acc[i][j][2]), "+f"(acc[i][j][3])
                    : "r"(a_frag[i][0]), "r"(a_frag[i][1]),
                      "r"(a_frag[i][2]), "r"(a_frag[i][3]),
                      "r"(b_frag[j][0]), "r"(b_frag[j][1]));
    }
}

// ---------------- mainloop over chunk range [c0, c1): single fp16 phase ----------------
__device__ __forceinline__ void mma_mainloop(
    const __half* A, const __half* B, int K, int c0, int c1, int m0, int n0,
    uint32_t smem_base, int t, int warpM, int warpN, int lane,
    float acc[4][8][4]) {
    int lrow = t >> 3, lkg = t & 7;
    uint32_t so = (uint32_t)lrow * 128u + (((uint32_t)lkg * 16u) ^ (((uint32_t)lrow & 7u) * 16u));
    size_t srcoff = (size_t)lrow * K + lkg * 8;
    size_t rbytes = (size_t)16 * K * 2;

    const __half* pA = A + (size_t)m0 * K + srcoff + (size_t)c0 * 64;
    const __half* pB = B + (size_t)n0 * K + srcoff + (size_t)c0 * 64;

    int la = lane & 15, lh = lane >> 4;
    uint32_t aoff[4], boff[4];
    #pragma unroll
    for (int i = 0; i < 4; i++) {
        uint32_t row = (uint32_t)(warpM * 64 + i * 16 + la);
        aoff[i] = row * 128u + (((uint32_t)lh * 16u) ^ ((row & 7u) * 16u));
    }
    #pragma unroll
    for (int jj = 0; jj < 4; jj++) {
        uint32_t row = (uint32_t)(warpN * 64 + jj * 16 + la);
        boff[jj] = 16384u + row * 128u + (((uint32_t)lh * 16u) ^ ((row & 7u) * 16u));
    }

#define ISSUE(slot) do { \
    uint32_t dst = smem_base + (uint32_t)(slot) * STAGE_BYTES; \
    const char* sa = (const char*)pA; const char* sb = (const char*)pB; \
    _Pragma("unroll") \
    for (int ii = 0; ii < 8; ii++) { \
        asm volatile("cp.async.cg.shared.global [%0], [%1], 16;" \
                     :: "r"(dst + so + (uint32_t)ii * 2048u), "l"(sa)); \
        asm volatile("cp.async.cg.shared.global [%0], [%1], 16;" \
                     :: "r"(dst + 16384u + so + (uint32_t)ii * 2048u), "l"(sb)); \
        sa += rbytes; sb += rbytes; } \
    pA += 64; pB += 64; } while(0)

    ISSUE(0); asm volatile("cp.async.commit_group;" ::: "memory");
    ISSUE(1); asm volatile("cp.async.commit_group;" ::: "memory");
    int stage = 0, pf_slot = 2;
    for (int kc = c0; kc < c1; kc++) {
        asm volatile("cp.async.wait_group 1;" ::: "memory");
        __syncthreads();
        if (kc + 2 < c1) {
            ISSUE(pf_slot);
            pf_slot = (pf_slot + 1 == NSTAGE) ? 0 : pf_slot + 1;
        }
        asm volatile("cp.async.commit_group;" ::: "memory");
        compute_stage(smem_base + (uint32_t)stage * STAGE_BYTES, aoff, boff, acc);
        stage = (stage + 1 == NSTAGE) ? 0 : stage + 1;
    }
#undef ISSUE
}

__device__ __forceinline__ float gelu_exact(float v) {
    return 0.5f * v * (1.0f + erff(v * 0.7071067811865476f));
}

// ---------------- GEMM1: h = gelu(A1 @ W1t^T + b); writes fp16 h; GRN sumsq ----------------
__global__ void __launch_bounds__(128, 2) gemm1_mma(int l, const float* __restrict__ bias) {
    extern __shared__ char smem[];
    uint32_t sbase = smem_u32(smem);
    int t = threadIdx.x, lane = t & 31, wid = t >> 5;
    int warpM = wid & 1, warpN = wid >> 1;           // 2x2 warps, 64x64 tiles
    int n0 = blockIdx.x * 128, m0 = blockIdx.y * 128;
    float acc[4][8][4] = {};
    mma_mainloop(g_a1, g_w1 + (size_t)l * INTER * DIM,
                 DIM, 0, 8, m0, n0, sbase, t, warpM, warpN, lane, acc);
    int b_lo = m0 / P1;
    int boundary = (b_lo + 1) * P1;
    float cs[2][8][2] = {};
    #pragma unroll
    for (int i = 0; i < 4; i++) {
        #pragma unroll
        for (int half = 0; half < 2; half++) {
            int r = m0 + warpM * 64 + i * 16 + (lane >> 2) + 8 * half;
            int bs = (r >= boundary) ? 1 : 0;
            int p = r - (bs ? boundary : b_lo * P1);
            int b = b_lo + bs;
            float wgt = (r >= M1) ? 0.0f :
                        ((p < 515) ? 1.0f : ((p == 515) ? CONST_W : 0.0f));
            bool wr_a2 = (r < M1) && (p < 512);
            size_t row2 = (size_t)(b * SEQ + p) * INTER;
            #pragma unroll
            for (int j = 0; j < 8; j++) {
                int n = n0 + warpN * 64 + j * 8 + (lane & 3) * 2;
                float g0 = gelu_exact(acc[i][j][half*2+0] + bias[n]);
                float g1 = gelu_exact(acc[i][j][half*2+1] + bias[n+1]);
                cs[bs][j][0] += wgt * g0 * g0;
                cs[bs][j][1] += wgt * g1 * g1;
                if (wr_a2) {
                    // GRN fast path: alpha==1, grn_b==0 -> A2 = h (alpha_fix repairs otherwise)
                    *(__half2*)&g_a2[row2 + n] =
                        __half2(__float2half_rn(g0), __float2half_rn(g1));
                }
            }
        }
    }
    #pragma unroll
    for (int bs = 0; bs < 2; bs++)
        #pragma unroll
        for (int j = 0; j < 8; j++)
            #pragma unroll
            for (int s = 0; s < 2; s++) {
                float v = cs[bs][j][s];
                v += __shfl_xor_sync(0xffffffffu, v, 4);
                v += __shfl_xor_sync(0xffffffffu, v, 8);
                v += __shfl_xor_sync(0xffffffffu, v, 16);
                cs[bs][j][s] = v;
            }
    if (lane < 4) {
        #pragma unroll
        for (int j = 0; j < 8; j++) {
            int n = n0 + warpN * 64 + j * 8 + lane * 2;
            atomicAdd(&g_sumsq[b_lo * INTER + n],     cs[0][j][0]);
            atomicAdd(&g_sumsq[b_lo * INTER + n + 1], cs[0][j][1]);
            if (b_lo + 1 < NB) {
                atomicAdd(&g_sumsq[(b_lo + 1) * INTER + n],     cs[1][j][0]);
                atomicAdd(&g_sumsq[(b_lo + 1) * INTER + n + 1], cs[1][j][1]);
            }
        }
    }
}

// ---------------- GEMM2: x += A2 @ W2t^T + b  (K-split 2, atomic epilogue) ----------------
__global__ void __launch_bounds__(128, 2) gemm2_mma(int l, const float* __restrict__ bias) {
    extern __shared__ char smem[];
    uint32_t sbase = smem_u32(smem);
    int t = threadIdx.x, lane = t & 31, wid = t >> 5;
    int warpM = wid & 1, warpN = wid >> 1;
    int n0 = blockIdx.x * 128, m0 = blockIdx.y * 128;
    int split = blockIdx.z;
    float acc[4][8][4] = {};
    mma_mainloop(g_a2, g_w2 + (size_t)l * DIM * INTER,
                 INTER, split * 8, split * 8 + 8, m0, n0,
                 sbase, t, warpM, warpN, lane, acc);
    #pragma unroll
    for (int i = 0; i < 4; i++) {
        int rowbase = m0 + warpM * 64 + i * 16 + (lane >> 2);
        #pragma unroll
        for (int half = 0; half < 2; half++) {
            int m = rowbase + 8 * half;
            #pragma unroll
            for (int j = 0; j < 8; j++) {
                int n = n0 + warpN * 64 + j * 8 + (lane & 3) * 2;
                size_t xo = (size_t)m * DIM + n;
                float add0 = acc[i][j][half*2+0];
                float add1 = acc[i][j][half*2+1];
                if (split == 0) { add0 += bias[n]; add1 += bias[n+1]; }
                atomicAdd(&g_x[xo],     add0);
                atomicAdd(&g_x[xo + 1], add1);
            }
        }
    }
}

// ---------------- fused prologue: embed (blocks 0..4095) + weight prep (rest) ----------------
__global__ void prep_embed_kernel(const int* __restrict__ text, const float* __restrict__ emb,
                                  const float* __restrict__ pw1_w, const float* __restrict__ pw2_w) {
    int blk = blockIdx.x;
    int t = threadIdx.x;               // 256
    if (blk < NB * SEQ) {
        // embed + abs pos enc (paired sincos)
        int p = blk & 511, b = blk >> 9;
        int tok = text[b * SEQ + p] + 1;
        const float* erow = emb + (size_t)tok * DIM;
        float* orow = g_x + (size_t)blk * DIM;
        float f   = expf(-9.210340371976184f * (float)t / 256.0f);
        float ang = (float)p * f;
        float sv, cv;
        sincosf(ang, &sv, &cv);
        orow[t]       = erow[t]       + cv;
        orow[t + 256] = erow[t + 256] + sv;
        return;
    }
    // weight transpose + fp16
    int pid = blk - NB * SEQ;
    int z = pid >> 10;                 // 1024 blocks per (l, which)
    int xy = pid & 1023;
    int cx = (xy & 31) * 32, ry = (xy >> 5) * 32;
    int which = z & 1, l = z >> 1;
    const float* src; __half* dh;
    int R, C;
    if (which == 0) { src = pw1_w + (size_t)l * DIM * INTER; R = DIM;  C = INTER;
                      dh = g_w1 + (size_t)l * INTER * DIM; }
    else            { src = pw2_w + (size_t)l * INTER * DIM; R = INTER; C = DIM;
                      dh = g_w2 + (size_t)l * DIM * INTER; }
    if (cx >= C || ry >= R) return;
    __shared__ float tl[32][33];
    int tx = t & 31, ty = t >> 5;      // (32, 8)
    #pragma unroll
    for (int i = 0; i < 4; i++)
        tl[ty * 4 + i][tx] = src[(size_t)(ry + ty * 4 + i) * C + cx + tx];
    __syncthreads();
    #pragma unroll
    for (int i = 0; i < 4; i++)
        dh[(size_t)(cx + ty * 4 + i) * R + ry + tx] = __float2half_rn(tl[tx][ty * 4 + i]);
}

// ---------------- dwconv(k=7) + LayerNorm -> fp16, 4 positions per block ----------------
__global__ void convln_kernel(const float* __restrict__ dw_w, const float* __restrict__ dw_b,
                              const float* __restrict__ ln_g, const float* __restrict__ ln_b) {
    int blk = blockIdx.x;              // NB * 129
    int b  = blk / 129;
    int p0 = (blk - b * 129) * 4;      // 0..512, handles p0..p0+3 (max 515)
    int t = threadIdx.x;               // 128
    // window rows p0-3 .. p0+6 for channels c = t + j*128
    float v[10][4];
    #pragma unroll
    for (int r = 0; r < 10; r++) {
        int pp = p0 - 3 + r;
        bool ok = (pp >= 0 && pp < SEQ);
        const float* row = g_x + (size_t)(b * SEQ + pp) * DIM;
        #pragma unroll
        for (int j = 0; j < 4; j++)
            v[r][j] = ok ? row[t + j * 128] : 0.0f;
    }
    float w[7][4], bw[4], lg[4], lb[4];
    #pragma unroll
    for (int j = 0; j < 4; j++) {
        int c = t + j * 128;
        bw[j] = dw_b[c]; lg[j] = ln_g[c]; lb[j] = ln_b[c];
        #pragma unroll
        for (int k = 0; k < 7; k++) w[k][j] = dw_w[k * DIM + c];
    }
    __shared__ float sh[8];
    int wrp = t >> 5;
    #pragma unroll
    for (int q = 0; q < 4; q++) {
        float y[4];
        #pragma unroll
        for (int j = 0; j < 4; j++) {
            float a = bw[j];
            #pragma unroll
            for (int k = 0; k < 7; k++) a += w[k][j] * v[q + k][j];
            y[j] = a;
        }
        float s  = y[0] + y[1] + y[2] + y[3];
        float s2 = y[0]*y[0] + y[1]*y[1] + y[2]*y[2] + y[3]*y[3];
        #pragma unroll
        for (int off = 16; off; off >>= 1) {
            s  += __shfl_xor_sync(0xffffffffu, s,  off);
            s2 += __shfl_xor_sync(0xffffffffu, s2, off);
        }
        if ((t & 31) == 0) { sh[wrp] = s; sh[4 + wrp] = s2; }
        __syncthreads();
        float S  = sh[0] + sh[1] + sh[2] + sh[3];
        float S2 = sh[4] + sh[5] + sh[6] + sh[7];
        __syncthreads();
        float mean = S * (1.0f/512.0f);
        float var  = S2 * (1.0f/512.0f) - mean * mean;
        float inv  = rsqrtf(var + 1e-6f);
        size_t base = (size_t)(b * P1 + p0 + q) * DIM;
        #pragma unroll
        for (int j = 0; j < 4; j++)
            g_a1[base + t + j * 128] = __float2half_rn((y[j] - mean) * inv * lg[j] + lb[j]);
    }
}

// ---------------- GRN finalize + in-place fixup (slow path only); resets sumsq ----------------
__global__ void alpha_fix_kernel(const float* __restrict__ grn_g, const float* __restrict__ grn_b) {
    int b = blockIdx.x;
    int i = threadIdx.x;               // 1024
    float gx = sqrtf(g_sumsq[b * INTER + i]);
    g_sumsq[b * INTER + i] = 0.0f;
    float r = gx;
    #pragma unroll
    for (int off = 16; off; off >>= 1) r += __shfl_xor_sync(0xffffffffu, r, off);
    __shared__ float sh[32];
    __shared__ float meansh;
    if ((i & 31) == 0) sh[i >> 5] = r;
    __syncthreads();
    if (i < 32) {
        float v = sh[i];
        #pragma unroll
        for (int off = 16; off; off >>= 1) v += __shfl_xor_sync(0xffffffffu, v, off);
        if (i == 0) meansh = v * (1.0f/1024.0f);
    }
    __syncthreads();
    float nx = gx / (meansh + 1e-6f);
    float alpha = grn_g[i] * nx + 1.0f;
    float gb = grn_b[i];
    int bad = (alpha != 1.0f) || (gb != 0.0f);
    if (!__syncthreads_or(bad)) return;   // GRN trivial: A2 already = h
    // slow path: rewrite all 512 rows of this batch in place
    __half* a2 = g_a2 + (size_t)(b * SEQ) * INTER + i;
    for (int p = 0; p < SEQ; p++) {
        float h = __half2float(a2[(size_t)p * INTER]);
        a2[(size_t)p * INTER] = __float2half_rn(alpha * h + gb);
    }
}

// ---------------- upsample ----------------
__global__ void upsample_kernel(const int* __restrict__ seq_len, float* __restrict__ out) {
    int bp = blockIdx.x;
    int b = bp >> 12, p = bp & 4095;
    int al = seq_len[b];
    float4* orow = (float4*)(out + (size_t)bp * DIM);
    if (p >= al) {
        for (int c = threadIdx.x; c < DIM / 4; c += blockDim.x)
            orow[c] = make_float4(0.f, 0.f, 0.f, 0.f);
        return;
    }
    int base  = al >> 9;
    int rem   = al & 511;
    int split = (512 - rem) * base;
    int j = (p < split) ? (p / base) : ((512 - rem) + (p - split) / (base + 1));
    if (j > 511) j = 511;
    const float4* xrow = (const float4*)(g_x + (size_t)(b * SEQ + j) * DIM);
    for (int c = threadIdx.x; c < DIM / 4; c += blockDim.x) orow[c] = xrow[c];
}

// ---------------- launch ----------------
extern "C" void kernel_launch(void* const* d_in, const int* in_sizes, int n_in,
                              void* d_out, int out_size) {
    const int*   text    = (const int*)  d_in[0];
    const int*   seq_len = (const int*)  d_in[1];
    const float* emb     = (const float*)d_in[2];
    const float* dw_w    = (const float*)d_in[3];
    const float* dw_b    = (const float*)d_in[4];
    const float* ln_g    = (const float*)d_in[5];
    const float* ln_b    = (const float*)d_in[6];
    const float* pw1_w   = (const float*)d_in[7];
    const float* pw1_b   = (const float*)d_in[8];
    const float* grn_g   = (const float*)d_in[9];
    const float* grn_b   = (const float*)d_in[10];
    const float* pw2_w   = (const float*)d_in[11];
    const float* pw2_b   = (const float*)d_in[12];
    float* out = (float*)d_out;

    static const int SMEM_BYTES = NSTAGE * (int)STAGE_BYTES;  // 96 KB
    cudaFuncSetAttribute(gemm1_mma, cudaFuncAttributeMaxDynamicSharedMemorySize, SMEM_BYTES);
    cudaFuncSetAttribute(gemm2_mma, cudaFuncAttributeMaxDynamicSharedMemorySize, SMEM_BYTES);

    prep_embed_kernel<<<NB * SEQ + 1024 * 2 * NLAYERS, 256>>>(text, emb, pw1_w, pw2_w);
    for (int l = 0; l < NLAYERS; l++) {
        convln_kernel<<<NB * 129, 128>>>(dw_w + l * 7 * DIM, dw_b + l * DIM,
                                         ln_g + l * DIM, ln_b + l * DIM);
        gemm1_mma<<<dim3(INTER / 128, M1T), 128, SMEM_BYTES>>>(l, pw1_b + l * INTER);
        alpha_fix_kernel<<<NB, 1024>>>(grn_g + l * INTER, grn_b + l * INTER);
        gemm2_mma<<<dim3(DIM / 128, NB * SEQ / 128, 2), 128, SMEM_BYTES>>>(l, pw2_b + l * DIM);
    }
    upsample_kernel<<<NB * MAXSEQ, 128>>>(seq_len, out);
}

// round 14
// speedup vs baseline: 1.1810x; 1.0369x over previous
#include <cuda_runtime.h>
#include <cuda_fp16.h>
#include <math.h>
#include <stdint.h>

#define NB 8
#define SEQ 512
#define MAXSEQ 4096
#define DIM 512
#define INTER 1024
#define NLAYERS 4
#define P1 516
#define M1 (NB*P1)            // 4128 gemm1 rows (packed)
#define M1T 33                // ceil(4128/128)
#define CONST_W 3581.0f

// ---------------- scratch ----------------
__device__ float  g_x   [NB*SEQ*DIM];
__device__ __half g_a1  [(M1T*128)*DIM];      // activations fp16 (rows >= 4128 stay zero)
__device__ __half g_a2  [NB*SEQ*INTER];
__device__ __half g_w1  [NLAYERS*INTER*DIM];  // pw1_w transposed [N][K], fp16
__device__ __half g_w2  [NLAYERS*DIM*INTER];  // pw2_w transposed [N][K], fp16
__device__ float  g_sumsq[NB*INTER];          // zero-init; only touched when grnflag set
__device__ int    g_grnflag[NLAYERS];         // per-layer: GRN non-trivial?

// ---------------- helpers ----------------
__device__ __forceinline__ uint32_t smem_u32(const void* p) {
    uint32_t a;
    asm("{ .reg .u64 t; cvta.to.shared.u64 t, %1; cvt.u32.u64 %0, t; }" : "=r"(a) : "l"(p));
    return a;
}

#define STAGE_BYTES 32768u      // A 16KB + B 16KB
#define NSTAGE 3

// ---------------- compute one 64-K stage: warp tile 64x64 (4 warps, 2x2) ----------------
__device__ __forceinline__ void compute_stage(uint32_t sbs,
                                              const uint32_t aoff[4], const uint32_t boff[4],
                                              float acc[4][8][4]) {
    #pragma unroll
    for (int ks = 0; ks < 4; ks++) {
        uint32_t kx = (uint32_t)ks * 32u;
        uint32_t a_frag[4][4];
        #pragma unroll
        for (int i = 0; i < 4; i++)
            asm volatile("ldmatrix.sync.aligned.m8n8.x4.shared.b16 {%0,%1,%2,%3}, [%4];"
                : "=r"(a_frag[i][0]), "=r"(a_frag[i][1]), "=r"(a_frag[i][2]), "=r"(a_frag[i][3])
                : "r"((sbs + aoff[i]) ^ kx));
        uint32_t b_frag[8][2];
        #pragma unroll
        for (int jj = 0; jj < 4; jj++) {
            uint32_t r0, r1, r2, r3;
            asm volatile("ldmatrix.sync.aligned.m8n8.x4.shared.b16 {%0,%1,%2,%3}, [%4];"
                : "=r"(r0), "=r"(r1), "=r"(r2), "=r"(r3) : "r"((sbs + boff[jj]) ^ kx));
            b_frag[jj*2+0][0] = r0; b_frag[jj*2+0][1] = r2;
            b_frag[jj*2+1][0] = r1; b_frag[jj*2+1][1] = r3;
        }
        #pragma unroll
        for (int i = 0; i < 4; i++)
            #pragma unroll
            for (int j = 0; j < 8; j++)
                asm volatile(
                    "mma.sync.aligned.m16n8k16.row.col.f32.f16.f16.f32 "
                    "{%0,%1,%2,%3}, {%4,%5,%6,%7}, {%8,%9}, {%0,%1,%2,%3};"
                    : "+f"(acc[i][j][0]), "+f"(acc[i][j][1]),
                      "+f"(acc[i][j][2]), "+f"(acc[i][j][3])
                    : "r"(a_frag[i][0]), "r"(a_frag[i][1]),
                      "r"(a_frag[i][2]), "r"(a_frag[i][3]),
                      "r"(b_frag[j][0]), "r"(b_frag[j][1]));
    }
}

// ---------------- mainloop over chunk range [c0, c1): single fp16 phase ----------------
__device__ __forceinline__ void mma_mainloop(
    const __half* A, const __half* B, int K, int c0, int c1, int m0, int n0,
    uint32_t smem_base, int t, int warpM, int warpN, int lane,
    float acc[4][8][4]) {
    int lrow = t >> 3, lkg = t & 7;
    uint32_t so = (uint32_t)lrow * 128u + (((uint32_t)lkg * 16u) ^ (((uint32_t)lrow & 7u) * 16u));
    size_t srcoff = (size_t)lrow * K + lkg * 8;
    size_t rbytes = (size_t)16 * K * 2;

    const __half* pA = A + (size_t)m0 * K + srcoff + (size_t)c0 * 64;
    const __half* pB = B + (size_t)n0 * K + srcoff + (size_t)c0 * 64;

    int la = lane & 15, lh = lane >> 4;
    uint32_t aoff[4], boff[4];
    #pragma unroll
    for (int i = 0; i < 4; i++) {
        uint32_t row = (uint32_t)(warpM * 64 + i * 16 + la);
        aoff[i] = row * 128u + (((uint32_t)lh * 16u) ^ ((row & 7u) * 16u));
    }
    #pragma unroll
    for (int jj = 0; jj < 4; jj++) {
        uint32_t row = (uint32_t)(warpN * 64 + jj * 16 + la);
        boff[jj] = 16384u + row * 128u + (((uint32_t)lh * 16u) ^ ((row & 7u) * 16u));
    }

#define ISSUE(slot) do { \
    uint32_t dst = smem_base + (uint32_t)(slot) * STAGE_BYTES; \
    const char* sa = (const char*)pA; const char* sb = (const char*)pB; \
    _Pragma("unroll") \
    for (int ii = 0; ii < 8; ii++) { \
        asm volatile("cp.async.cg.shared.global [%0], [%1], 16;" \
                     :: "r"(dst + so + (uint32_t)ii * 2048u), "l"(sa)); \
        asm volatile("cp.async.cg.shared.global [%0], [%1], 16;" \
                     :: "r"(dst + 16384u + so + (uint32_t)ii * 2048u), "l"(sb)); \
        sa += rbytes; sb += rbytes; } \
    pA += 64; pB += 64; } while(0)

    ISSUE(0); asm volatile("cp.async.commit_group;" ::: "memory");
    ISSUE(1); asm volatile("cp.async.commit_group;" ::: "memory");
    int stage = 0, pf_slot = 2;
    for (int kc = c0; kc < c1; kc++) {
        asm volatile("cp.async.wait_group 1;" ::: "memory");
        __syncthreads();
        if (kc + 2 < c1) {
            ISSUE(pf_slot);
            pf_slot = (pf_slot + 1 == NSTAGE) ? 0 : pf_slot + 1;
        }
        asm volatile("cp.async.commit_group;" ::: "memory");
        compute_stage(smem_base + (uint32_t)stage * STAGE_BYTES, aoff, boff, acc);
        stage = (stage + 1 == NSTAGE) ? 0 : stage + 1;
    }
#undef ISSUE
}

__device__ __forceinline__ float gelu_exact(float v) {
    return 0.5f * v * (1.0f + erff(v * 0.7071067811865476f));
}

// ---------------- GEMM1: h = gelu(A1 @ W1t^T + b); writes fp16 h; GRN sumsq (flag-guarded) ----------------
__global__ void __launch_bounds__(128, 2) gemm1_mma(int l, const float* __restrict__ bias) {
    extern __shared__ char smem[];
    uint32_t sbase = smem_u32(smem);
    int t = threadIdx.x, lane = t & 31, wid = t >> 5;
    int warpM = wid & 1, warpN = wid >> 1;           // 2x2 warps, 64x64 tiles
    int n0 = blockIdx.x * 128, m0 = blockIdx.y * 128;
    float acc[4][8][4] = {};
    mma_mainloop(g_a1, g_w1 + (size_t)l * INTER * DIM,
                 DIM, 0, 8, m0, n0, sbase, t, warpM, warpN, lane, acc);
    int b_lo = m0 / P1;
    int boundary = (b_lo + 1) * P1;
    float cs[2][8][2] = {};
    #pragma unroll
    for (int i = 0; i < 4; i++) {
        #pragma unroll
        for (int half = 0; half < 2; half++) {
            int r = m0 + warpM * 64 + i * 16 + (lane >> 2) + 8 * half;
            int bs = (r >= boundary) ? 1 : 0;
            int p = r - (bs ? boundary : b_lo * P1);
            int b = b_lo + bs;
            float wgt = (r >= M1) ? 0.0f :
                        ((p < 515) ? 1.0f : ((p == 515) ? CONST_W : 0.0f));
            bool wr_a2 = (r < M1) && (p < 512);
            size_t row2 = (size_t)(b * SEQ + p) * INTER;
            #pragma unroll
            for (int j = 0; j < 8; j++) {
                int n = n0 + warpN * 64 + j * 8 + (lane & 3) * 2;
                float g0 = gelu_exact(acc[i][j][half*2+0] + bias[n]);
                float g1 = gelu_exact(acc[i][j][half*2+1] + bias[n+1]);
                cs[bs][j][0] += wgt * g0 * g0;
                cs[bs][j][1] += wgt * g1 * g1;
                if (wr_a2) {
                    // GRN fast path: alpha==1, grn_b==0 -> A2 = h (alpha_fix repairs otherwise)
                    *(__half2*)&g_a2[row2 + n] =
                        __half2(__float2half_rn(g0), __float2half_rn(g1));
                }
            }
        }
    }
    if (g_grnflag[l]) {      // sumsq only needed when GRN non-trivial
        #pragma unroll
        for (int bs = 0; bs < 2; bs++)
            #pragma unroll
            for (int j = 0; j < 8; j++)
                #pragma unroll
                for (int s = 0; s < 2; s++) {
                    float v = cs[bs][j][s];
                    v += __shfl_xor_sync(0xffffffffu, v, 4);
                    v += __shfl_xor_sync(0xffffffffu, v, 8);
                    v += __shfl_xor_sync(0xffffffffu, v, 16);
                    cs[bs][j][s] = v;
                }
        if (lane < 4) {
            #pragma unroll
            for (int j = 0; j < 8; j++) {
                int n = n0 + warpN * 64 + j * 8 + lane * 2;
                atomicAdd(&g_sumsq[b_lo * INTER + n],     cs[0][j][0]);
                atomicAdd(&g_sumsq[b_lo * INTER + n + 1], cs[0][j][1]);
                if (b_lo + 1 < NB) {
                    atomicAdd(&g_sumsq[(b_lo + 1) * INTER + n],     cs[1][j][0]);
                    atomicAdd(&g_sumsq[(b_lo + 1) * INTER + n + 1], cs[1][j][1]);
                }
            }
        }
    }
}

// ---------------- GEMM2: x += A2 @ W2t^T + b  (K-split 2, atomic epilogue) ----------------
__global__ void __launch_bounds__(128, 2) gemm2_mma(int l, const float* __restrict__ bias) {
    extern __shared__ char smem[];
    uint32_t sbase = smem_u32(smem);
    int t = threadIdx.x, lane = t & 31, wid = t >> 5;
    int warpM = wid & 1, warpN = wid >> 1;
    int n0 = blockIdx.x * 128, m0 = blockIdx.y * 128;
    int split = blockIdx.z;
    float acc[4][8][4] = {};
    mma_mainloop(g_a2, g_w2 + (size_t)l * DIM * INTER,
                 INTER, split * 8, split * 8 + 8, m0, n0,
                 sbase, t, warpM, warpN, lane, acc);
    #pragma unroll
    for (int i = 0; i < 4; i++) {
        int rowbase = m0 + warpM * 64 + i * 16 + (lane >> 2);
        #pragma unroll
        for (int half = 0; half < 2; half++) {
            int m = rowbase + 8 * half;
            #pragma unroll
            for (int j = 0; j < 8; j++) {
                int n = n0 + warpN * 64 + j * 8 + (lane & 3) * 2;
                size_t xo = (size_t)m * DIM + n;
                float add0 = acc[i][j][half*2+0];
                float add1 = acc[i][j][half*2+1];
                if (split == 0) { add0 += bias[n]; add1 += bias[n+1]; }
                atomicAdd(&g_x[xo],     add0);
                atomicAdd(&g_x[xo + 1], add1);
            }
        }
    }
}

// ---------------- fused prologue: embed + weight prep + GRN-flag scan ----------------
__global__ void prep_embed_kernel(const int* __restrict__ text, const float* __restrict__ emb,
                                  const float* __restrict__ pw1_w, const float* __restrict__ pw2_w,
                                  const float* __restrict__ grn_g, const float* __restrict__ grn_b) {
    int blk = blockIdx.x;
    int t = threadIdx.x;               // 256
    if (blk < NB * SEQ) {
        // embed + abs pos enc (paired sincos)
        int p = blk & 511, b = blk >> 9;
        int tok = text[b * SEQ + p] + 1;
        const float* erow = emb + (size_t)tok * DIM;
        float* orow = g_x + (size_t)blk * DIM;
        float f   = expf(-9.210340371976184f * (float)t / 256.0f);
        float ang = (float)p * f;
        float sv, cv;
        sincosf(ang, &sv, &cv);
        orow[t]       = erow[t]       + cv;
        orow[t + 256] = erow[t + 256] + sv;
        return;
    }
    int pid = blk - NB * SEQ;
    if (pid >= 1024 * 2 * NLAYERS) {
        // GRN-flag scan: one block per layer
        int l = pid - 1024 * 2 * NLAYERS;
        const float* gg = grn_g + l * INTER;
        const float* gb = grn_b + l * INTER;
        int bad = 0;
        #pragma unroll
        for (int i = 0; i < 4; i++) {
            int c = t + i * 256;
            bad |= (gg[c] != 0.0f) || (gb[c] != 0.0f);
        }
        int any = __syncthreads_or(bad);
        if (t == 0) g_grnflag[l] = any;
        return;
    }
    // weight transpose + fp16
    int z = pid >> 10;                 // 1024 blocks per (l, which)
    int xy = pid & 1023;
    int cx = (xy & 31) * 32, ry = (xy >> 5) * 32;
    int which = z & 1, l = z >> 1;
    const float* src; __half* dh;
    int R, C;
    if (which == 0) { src = pw1_w + (size_t)l * DIM * INTER; R = DIM;  C = INTER;
                      dh = g_w1 + (size_t)l * INTER * DIM; }
    else            { src = pw2_w + (size_t)l * INTER * DIM; R = INTER; C = DIM;
                      dh = g_w2 + (size_t)l * DIM * INTER; }
    if (cx >= C || ry >= R) return;
    __shared__ float tl[32][33];
    int tx = t & 31, ty = t >> 5;      // (32, 8)
    #pragma unroll
    for (int i = 0; i < 4; i++)
        tl[ty * 4 + i][tx] = src[(size_t)(ry + ty * 4 + i) * C + cx + tx];
    __syncthreads();
    #pragma unroll
    for (int i = 0; i < 4; i++)
        dh[(size_t)(cx + ty * 4 + i) * R + ry + tx] = __float2half_rn(tl[tx][ty * 4 + i]);
}

// ---------------- dwconv(k=7) + LayerNorm -> fp16, 4 positions per block ----------------
__global__ void convln_kernel(const float* __restrict__ dw_w, const float* __restrict__ dw_b,
                              const float* __restrict__ ln_g, const float* __restrict__ ln_b) {
    int blk = blockIdx.x;              // NB * 129
    int b  = blk / 129;
    int p0 = (blk - b * 129) * 4;      // 0..512, handles p0..p0+3 (max 515)
    int t = threadIdx.x;               // 128
    float v[10][4];
    #pragma unroll
    for (int r = 0; r < 10; r++) {
        int pp = p0 - 3 + r;
        bool ok = (pp >= 0 && pp < SEQ);
        const float* row = g_x + (size_t)(b * SEQ + pp) * DIM;
        #pragma unroll
        for (int j = 0; j < 4; j++)
            v[r][j] = ok ? row[t + j * 128] : 0.0f;
    }
    float w[7][4], bw[4], lg[4], lb[4];
    #pragma unroll
    for (int j = 0; j < 4; j++) {
        int c = t + j * 128;
        bw[j] = dw_b[c]; lg[j] = ln_g[c]; lb[j] = ln_b[c];
        #pragma unroll
        for (int k = 0; k < 7; k++) w[k][j] = dw_w[k * DIM + c];
    }
    __shared__ float sh[8];
    int wrp = t >> 5;
    #pragma unroll
    for (int q = 0; q < 4; q++) {
        float y[4];
        #pragma unroll
        for (int j = 0; j < 4; j++) {
            float a = bw[j];
            #pragma unroll
            for (int k = 0; k < 7; k++) a += w[k][j] * v[q + k][j];
            y[j] = a;
        }
        float s  = y[0] + y[1] + y[2] + y[3];
        float s2 = y[0]*y[0] + y[1]*y[1] + y[2]*y[2] + y[3]*y[3];
        #pragma unroll
        for (int off = 16; off; off >>= 1) {
            s  += __shfl_xor_sync(0xffffffffu, s,  off);
            s2 += __shfl_xor_sync(0xffffffffu, s2, off);
        }
        if ((t & 31) == 0) { sh[wrp] = s; sh[4 + wrp] = s2; }
        __syncthreads();
        float S  = sh[0] + sh[1] + sh[2] + sh[3];
        float S2 = sh[4] + sh[5] + sh[6] + sh[7];
        __syncthreads();
        float mean = S * (1.0f/512.0f);
        float var  = S2 * (1.0f/512.0f) - mean * mean;
        float inv  = rsqrtf(var + 1e-6f);
        size_t base = (size_t)(b * P1 + p0 + q) * DIM;
        #pragma unroll
        for (int j = 0; j < 4; j++)
            g_a1[base + t + j * 128] = __float2half_rn((y[j] - mean) * inv * lg[j] + lb[j]);
    }
}

// ---------------- GRN finalize + in-place fixup (slow path only); flag-guarded ----------------
__global__ void alpha_fix_kernel(int l, const float* __restrict__ grn_g,
                                 const float* __restrict__ grn_b) {
    if (!g_grnflag[l]) return;         // GRN trivial: A2 already = h, sumsq untouched (zero)
    int b = blockIdx.x;
    int i = threadIdx.x;               // 1024
    float gx = sqrtf(g_sumsq[b * INTER + i]);
    g_sumsq[b * INTER + i] = 0.0f;
    float r = gx;
    #pragma unroll
    for (int off = 16; off; off >>= 1) r += __shfl_xor_sync(0xffffffffu, r, off);
    __shared__ float sh[32];
    __shared__ float meansh;
    if ((i & 31) == 0) sh[i >> 5] = r;
    __syncthreads();
    if (i < 32) {
        float v = sh[i];
        #pragma unroll
        for (int off = 16; off; off >>= 1) v += __shfl_xor_sync(0xffffffffu, v, off);
        if (i == 0) meansh = v * (1.0f/1024.0f);
    }
    __syncthreads();
    float nx = gx / (meansh + 1e-6f);
    float alpha = grn_g[i] * nx + 1.0f;
    float gb = grn_b[i];
    __half* a2 = g_a2 + (size_t)(b * SEQ) * INTER + i;
    for (int p = 0; p < SEQ; p++) {
        float h = __half2float(a2[(size_t)p * INTER]);
        a2[(size_t)p * INTER] = __float2half_rn(alpha * h + gb);
    }
}

// ---------------- upsample ----------------
__global__ void upsample_kernel(const int* __restrict__ seq_len, float* __restrict__ out) {
    int bp = blockIdx.x;
    int b = bp >> 12, p = bp & 4095;
    int al = seq_len[b];
    float4* orow = (float4*)(out + (size_t)bp * DIM);
    if (p >= al) {
        for (int c = threadIdx.x; c < DIM / 4; c += blockDim.x)
            orow[c] = make_float4(0.f, 0.f, 0.f, 0.f);
        return;
    }
    int base  = al >> 9;
    int rem   = al & 511;
    int split = (512 - rem) * base;
    int j = (p < split) ? (p / base) : ((512 - rem) + (p - split) / (base + 1));
    if (j > 511) j = 511;
    const float4* xrow = (const float4*)(g_x + (size_t)(b * SEQ + j) * DIM);
    for (int c = threadIdx.x; c < DIM / 4; c += blockDim.x) orow[c] = xrow[c];
}

// ---------------- launch ----------------
extern "C" void kernel_launch(void* const* d_in, const int* in_sizes, int n_in,
                              void* d_out, int out_size) {
    const int*   text    = (const int*)  d_in[0];
    const int*   seq_len = (const int*)  d_in[1];
    const float* emb     = (const float*)d_in[2];
    const float* dw_w    = (const float*)d_in[3];
    const float* dw_b    = (const float*)d_in[4];
    const float* ln_g    = (const float*)d_in[5];
    const float* ln_b    = (const float*)d_in[6];
    const float* pw1_w   = (const float*)d_in[7];
    const float* pw1_b   = (const float*)d_in[8];
    const float* grn_g   = (const float*)d_in[9];
    const float* grn_b   = (const float*)d_in[10];
    const float* pw2_w   = (const float*)d_in[11];
    const float* pw2_b   = (const float*)d_in[12];
    float* out = (float*)d_out;

    static const int SMEM_BYTES = NSTAGE * (int)STAGE_BYTES;  // 96 KB
    cudaFuncSetAttribute(gemm1_mma, cudaFuncAttributeMaxDynamicSharedMemorySize, SMEM_BYTES);
    cudaFuncSetAttribute(gemm2_mma, cudaFuncAttributeMaxDynamicSharedMemorySize, SMEM_BYTES);

    prep_embed_kernel<<<NB * SEQ + 1024 * 2 * NLAYERS + NLAYERS, 256>>>(
        text, emb, pw1_w, pw2_w, grn_g, grn_b);
    for (int l = 0; l < NLAYERS; l++) {
        convln_kernel<<<NB * 129, 128>>>(dw_w + l * 7 * DIM, dw_b + l * DIM,
                                         ln_g + l * DIM, ln_b + l * DIM);
        gemm1_mma<<<dim3(INTER / 128, M1T), 128, SMEM_BYTES>>>(l, pw1_b + l * INTER);
        alpha_fix_kernel<<<NB, 1024>>>(l, grn_g + l * INTER, grn_b + l * INTER);
        gemm2_mma<<<dim3(DIM / 128, NB * SEQ / 128, 2), 128, SMEM_BYTES>>>(l, pw2_b + l * DIM);
    }
    upsample_kernel<<<NB * MAXSEQ, 128>>>(seq_len, out);
}

// round 17
// speedup vs baseline: 1.2267x; 1.0387x over previous
#include <cuda_runtime.h>
#include <cuda_fp16.h>
#include <math.h>
#include <stdint.h>

#define NB 8
#define SEQ 512
#define MAXSEQ 4096
#define DIM 512
#define INTER 1024
#define NLAYERS 4
#define P1 516
#define M1 (NB*P1)            // 4128 gemm1 rows (packed)
#define M1T 33                // ceil(4128/128)
#define CONST_W 3581.0f

// ---------------- scratch ----------------
__device__ float  g_x   [NB*SEQ*DIM];
__device__ __half g_a1  [(M1T*128)*DIM];      // activations fp16 (rows >= 4128 stay zero)
__device__ __half g_a2  [NB*SEQ*INTER];
__device__ __half g_w1  [NLAYERS*INTER*DIM];  // pw1_w transposed [N][K], fp16
__device__ __half g_w2  [NLAYERS*DIM*INTER];  // pw2_w transposed [N][K], fp16
__device__ float  g_sumsq[NB*INTER];          // zero-init; only touched when grnflag set
__device__ int    g_grnflag[NLAYERS];         // per-layer: GRN non-trivial?

// ---------------- helpers ----------------
__device__ __forceinline__ uint32_t smem_u32(const void* p) {
    uint32_t a;
    asm("{ .reg .u64 t; cvta.to.shared.u64 t, %1; cvt.u32.u64 %0, t; }" : "=r"(a) : "l"(p));
    return a;
}

#define STAGE_BYTES 32768u      // A 16KB + B 16KB
#define NSTAGE 3

// ---------------- compute one 64-K stage: warp tile 64x64 (4 warps, 2x2) ----------------
__device__ __forceinline__ void compute_stage(uint32_t sbs,
                                              const uint32_t aoff[4], const uint32_t boff[4],
                                              float acc[4][8][4]) {
    #pragma unroll
    for (int ks = 0; ks < 4; ks++) {
        uint32_t kx = (uint32_t)ks * 32u;
        uint32_t a_frag[4][4];
        #pragma unroll
        for (int i = 0; i < 4; i++)
            asm volatile("ldmatrix.sync.aligned.m8n8.x4.shared.b16 {%0,%1,%2,%3}, [%4];"
                : "=r"(a_frag[i][0]), "=r"(a_frag[i][1]), "=r"(a_frag[i][2]), "=r"(a_frag[i][3])
                : "r"((sbs + aoff[i]) ^ kx));
        uint32_t b_frag[8][2];
        #pragma unroll
        for (int jj = 0; jj < 4; jj++) {
            uint32_t r0, r1, r2, r3;
            asm volatile("ldmatrix.sync.aligned.m8n8.x4.shared.b16 {%0,%1,%2,%3}, [%4];"
                : "=r"(r0), "=r"(r1), "=r"(r2), "=r"(r3) : "r"((sbs + boff[jj]) ^ kx));
            b_frag[jj*2+0][0] = r0; b_frag[jj*2+0][1] = r2;
            b_frag[jj*2+1][0] = r1; b_frag[jj*2+1][1] = r3;
        }
        #pragma unroll
        for (int i = 0; i < 4; i++)
            #pragma unroll
            for (int j = 0; j < 8; j++)
                asm volatile(
                    "mma.sync.aligned.m16n8k16.row.col.f32.f16.f16.f32 "
                    "{%0,%1,%2,%3}, {%4,%5,%6,%7}, {%8,%9}, {%0,%1,%2,%3};"
                    : "+f"(acc[i][j][0]), "+f"(acc[i][j][1]),
                      "+f"(acc[i][j][2]), "+f"(acc[i][j][3])
                    : "r"(a_frag[i][0]), "r"(a_frag[i][1]),
                      "r"(a_frag[i][2]), "r"(a_frag[i][3]),
                      "r"(b_frag[j][0]), "r"(b_frag[j][1]));
    }
}

// ---------------- mainloop over chunk range [c0, c1): single fp16 phase ----------------
__device__ __forceinline__ void mma_mainloop(
    const __half* A, const __half* B, int K, int c0, int c1, int m0, int n0,
    uint32_t smem_base, int t, int warpM, int warpN, int lane,
    float acc[4][8][4]) {
    int lrow = t >> 3, lkg = t & 7;
    uint32_t so = (uint32_t)lrow * 128u + (((uint32_t)lkg * 16u) ^ (((uint32_t)lrow & 7u) * 16u));
    size_t srcoff = (size_t)lrow * K + lkg * 8;
    size_t rbytes = (size_t)16 * K * 2;

    const __half* pA = A + (size_t)m0 * K + srcoff + (size_t)c0 * 64;
    const __half* pB = B + (size_t)n0 * K + srcoff + (size_t)c0 * 64;

    int la = lane & 15, lh = lane >> 4;
    uint32_t aoff[4], boff[4];
    #pragma unroll
    for (int i = 0; i < 4; i++) {
        uint32_t row = (uint32_t)(warpM * 64 + i * 16 + la);
        aoff[i] = row * 128u + (((uint32_t)lh * 16u) ^ ((row & 7u) * 16u));
    }
    #pragma unroll
    for (int jj = 0; jj < 4; jj++) {
        uint32_t row = (uint32_t)(warpN * 64 + jj * 16 + la);
        boff[jj] = 16384u + row * 128u + (((uint32_t)lh * 16u) ^ ((row & 7u) * 16u));
    }

#define ISSUE(slot) do { \
    uint32_t dst = smem_base + (uint32_t)(slot) * STAGE_BYTES; \
    const char* sa = (const char*)pA; const char* sb = (const char*)pB; \
    _Pragma("unroll") \
    for (int ii = 0; ii < 8; ii++) { \
        asm volatile("cp.async.cg.shared.global [%0], [%1], 16;" \
                     :: "r"(dst + so + (uint32_t)ii * 2048u), "l"(sa)); \
        asm volatile("cp.async.cg.shared.global [%0], [%1], 16;" \
                     :: "r"(dst + 16384u + so + (uint32_t)ii * 2048u), "l"(sb)); \
        sa += rbytes; sb += rbytes; } \
    pA += 64; pB += 64; } while(0)

    ISSUE(0); asm volatile("cp.async.commit_group;" ::: "memory");
    ISSUE(1); asm volatile("cp.async.commit_group;" ::: "memory");
    int stage = 0, pf_slot = 2;
    for (int kc = c0; kc < c1; kc++) {
        asm volatile("cp.async.wait_group 1;" ::: "memory");
        __syncthreads();
        if (kc + 2 < c1) {
            ISSUE(pf_slot);
            pf_slot = (pf_slot + 1 == NSTAGE) ? 0 : pf_slot + 1;
        }
        asm volatile("cp.async.commit_group;" ::: "memory");
        compute_stage(smem_base + (uint32_t)stage * STAGE_BYTES, aoff, boff, acc);
        stage = (stage + 1 == NSTAGE) ? 0 : stage + 1;
    }
#undef ISSUE
}

__device__ __forceinline__ float gelu_exact(float v) {
    return 0.5f * v * (1.0f + erff(v * 0.7071067811865476f));
}

// ---------------- GEMM1: h = gelu(A1 @ W1t^T + b); writes fp16 h; GRN sumsq (flag-guarded) ----------------
__global__ void __launch_bounds__(128, 2) gemm1_mma(int l, const float* __restrict__ bias) {
    extern __shared__ char smem[];
    uint32_t sbase = smem_u32(smem);
    int t = threadIdx.x, lane = t & 31, wid = t >> 5;
    int warpM = wid & 1, warpN = wid >> 1;           // 2x2 warps, 64x64 tiles
    int n0 = blockIdx.x * 128, m0 = blockIdx.y * 128;
    float acc[4][8][4] = {};
    mma_mainloop(g_a1, g_w1 + (size_t)l * INTER * DIM,
                 DIM, 0, 8, m0, n0, sbase, t, warpM, warpN, lane, acc);
    int b_lo = m0 / P1;
    int boundary = (b_lo + 1) * P1;
    float cs[2][8][2] = {};
    #pragma unroll
    for (int i = 0; i < 4; i++) {
        #pragma unroll
        for (int half = 0; half < 2; half++) {
            int r = m0 + warpM * 64 + i * 16 + (lane >> 2) + 8 * half;
            int bs = (r >= boundary) ? 1 : 0;
            int p = r - (bs ? boundary : b_lo * P1);
            int b = b_lo + bs;
            float wgt = (r >= M1) ? 0.0f :
                        ((p < 515) ? 1.0f : ((p == 515) ? CONST_W : 0.0f));
            bool wr_a2 = (r < M1) && (p < 512);
            size_t row2 = (size_t)(b * SEQ + p) * INTER;
            #pragma unroll
            for (int j = 0; j < 8; j++) {
                int n = n0 + warpN * 64 + j * 8 + (lane & 3) * 2;
                float g0 = gelu_exact(acc[i][j][half*2+0] + bias[n]);
                float g1 = gelu_exact(acc[i][j][half*2+1] + bias[n+1]);
                cs[bs][j][0] += wgt * g0 * g0;
                cs[bs][j][1] += wgt * g1 * g1;
                if (wr_a2) {
                    // GRN fast path: alpha==1, grn_b==0 -> A2 = h (alpha_fix repairs otherwise)
                    *(__half2*)&g_a2[row2 + n] =
                        __half2(__float2half_rn(g0), __float2half_rn(g1));
                }
            }
        }
    }
    if (g_grnflag[l]) {      // sumsq only needed when GRN non-trivial
        #pragma unroll
        for (int bs = 0; bs < 2; bs++)
            #pragma unroll
            for (int j = 0; j < 8; j++)
                #pragma unroll
                for (int s = 0; s < 2; s++) {
                    float v = cs[bs][j][s];
                    v += __shfl_xor_sync(0xffffffffu, v, 4);
                    v += __shfl_xor_sync(0xffffffffu, v, 8);
                    v += __shfl_xor_sync(0xffffffffu, v, 16);
                    cs[bs][j][s] = v;
                }
        if (lane < 4) {
            #pragma unroll
            for (int j = 0; j < 8; j++) {
                int n = n0 + warpN * 64 + j * 8 + lane * 2;
                atomicAdd(&g_sumsq[b_lo * INTER + n],     cs[0][j][0]);
                atomicAdd(&g_sumsq[b_lo * INTER + n + 1], cs[0][j][1]);
                if (b_lo + 1 < NB) {
                    atomicAdd(&g_sumsq[(b_lo + 1) * INTER + n],     cs[1][j][0]);
                    atomicAdd(&g_sumsq[(b_lo + 1) * INTER + n + 1], cs[1][j][1]);
                }
            }
        }
    }
}

// ---------------- GEMM2: x += A2 @ W2t^T + b  (K-split 2, atomic epilogue) ----------------
__global__ void __launch_bounds__(128, 2) gemm2_mma(int l, const float* __restrict__ bias) {
    extern __shared__ char smem[];
    uint32_t sbase = smem_u32(smem);
    int t = threadIdx.x, lane = t & 31, wid = t >> 5;
    int warpM = wid & 1, warpN = wid >> 1;
    int n0 = blockIdx.x * 128, m0 = blockIdx.y * 128;
    int split = blockIdx.z;
    float acc[4][8][4] = {};
    mma_mainloop(g_a2, g_w2 + (size_t)l * DIM * INTER,
                 INTER, split * 8, split * 8 + 8, m0, n0,
                 sbase, t, warpM, warpN, lane, acc);
    #pragma unroll
    for (int i = 0; i < 4; i++) {
        int rowbase = m0 + warpM * 64 + i * 16 + (lane >> 2);
        #pragma unroll
        for (int half = 0; half < 2; half++) {
            int m = rowbase + 8 * half;
            #pragma unroll
            for (int j = 0; j < 8; j++) {
                int n = n0 + warpN * 64 + j * 8 + (lane & 3) * 2;
                size_t xo = (size_t)m * DIM + n;
                float add0 = acc[i][j][half*2+0];
                float add1 = acc[i][j][half*2+1];
                if (split == 0) { add0 += bias[n]; add1 += bias[n+1]; }
                atomicAdd(&g_x[xo],     add0);
                atomicAdd(&g_x[xo + 1], add1);
            }
        }
    }
}

// ---------------- fused prologue: embed + weight prep + GRN-flag scan ----------------
__global__ void prep_embed_kernel(const int* __restrict__ text, const float* __restrict__ emb,
                                  const float* __restrict__ pw1_w, const float* __restrict__ pw2_w,
                                  const float* __restrict__ grn_g, const float* __restrict__ grn_b) {
    int blk = blockIdx.x;
    int t = threadIdx.x;               // 256
    if (blk < NB * SEQ) {
        int p = blk & 511, b = blk >> 9;
        int tok = text[b * SEQ + p] + 1;
        const float* erow = emb + (size_t)tok * DIM;
        float* orow = g_x + (size_t)blk * DIM;
        float f   = expf(-9.210340371976184f * (float)t / 256.0f);
        float ang = (float)p * f;
        float sv, cv;
        sincosf(ang, &sv, &cv);
        orow[t]       = erow[t]       + cv;
        orow[t + 256] = erow[t + 256] + sv;
        return;
    }
    int pid = blk - NB * SEQ;
    if (pid >= 1024 * 2 * NLAYERS) {
        int l = pid - 1024 * 2 * NLAYERS;
        const float* gg = grn_g + l * INTER;
        const float* gb = grn_b + l * INTER;
        int bad = 0;
        #pragma unroll
        for (int i = 0; i < 4; i++) {
            int c = t + i * 256;
            bad |= (gg[c] != 0.0f) || (gb[c] != 0.0f);
        }
        int any = __syncthreads_or(bad);
        if (t == 0) g_grnflag[l] = any;
        return;
    }
    int z = pid >> 10;
    int xy = pid & 1023;
    int cx = (xy & 31) * 32, ry = (xy >> 5) * 32;
    int which = z & 1, l = z >> 1;
    const float* src; __half* dh;
    int R, C;
    if (which == 0) { src = pw1_w + (size_t)l * DIM * INTER; R = DIM;  C = INTER;
                      dh = g_w1 + (size_t)l * INTER * DIM; }
    else            { src = pw2_w + (size_t)l * INTER * DIM; R = INTER; C = DIM;
                      dh = g_w2 + (size_t)l * DIM * INTER; }
    if (cx >= C || ry >= R) return;
    __shared__ float tl[32][33];
    int tx = t & 31, ty = t >> 5;
    #pragma unroll
    for (int i = 0; i < 4; i++)
        tl[ty * 4 + i][tx] = src[(size_t)(ry + ty * 4 + i) * C + cx + tx];
    __syncthreads();
    #pragma unroll
    for (int i = 0; i < 4; i++)
        dh[(size_t)(cx + ty * 4 + i) * R + ry + tx] = __float2half_rn(tl[tx][ty * 4 + i]);
}

// ---------------- dwconv(k=7) + LayerNorm -> fp16, 4 positions per block ----------------
__global__ void convln_kernel(const float* __restrict__ dw_w, const float* __restrict__ dw_b,
                              const float* __restrict__ ln_g, const float* __restrict__ ln_b) {
    int blk = blockIdx.x;              // NB * 129
    int b  = blk / 129;
    int p0 = (blk - b * 129) * 4;
    int t = threadIdx.x;               // 128
    float v[10][4];
    #pragma unroll
    for (int r = 0; r < 10; r++) {
        int pp = p0 - 3 + r;
        bool ok = (pp >= 0 && pp < SEQ);
        const float* row = g_x + (size_t)(b * SEQ + pp) * DIM;
        #pragma unroll
        for (int j = 0; j < 4; j++)
            v[r][j] = ok ? row[t + j * 128] : 0.0f;
    }
    float w[7][4], bw[4], lg[4], lb[4];
    #pragma unroll
    for (int j = 0; j < 4; j++) {
        int c = t + j * 128;
        bw[j] = dw_b[c]; lg[j] = ln_g[c]; lb[j] = ln_b[c];
        #pragma unroll
        for (int k = 0; k < 7; k++) w[k][j] = dw_w[k * DIM + c];
    }
    __shared__ float sh[8];
    int wrp = t >> 5;
    #pragma unroll
    for (int q = 0; q < 4; q++) {
        float y[4];
        #pragma unroll
        for (int j = 0; j < 4; j++) {
            float a = bw[j];
            #pragma unroll
            for (int k = 0; k < 7; k++) a += w[k][j] * v[q + k][j];
            y[j] = a;
        }
        float s  = y[0] + y[1] + y[2] + y[3];
        float s2 = y[0]*y[0] + y[1]*y[1] + y[2]*y[2] + y[3]*y[3];
        #pragma unroll
        for (int off = 16; off; off >>= 1) {
            s  += __shfl_xor_sync(0xffffffffu, s,  off);
            s2 += __shfl_xor_sync(0xffffffffu, s2, off);
        }
        if ((t & 31) == 0) { sh[wrp] = s; sh[4 + wrp] = s2; }
        __syncthreads();
        float S  = sh[0] + sh[1] + sh[2] + sh[3];
        float S2 = sh[4] + sh[5] + sh[6] + sh[7];
        __syncthreads();
        float mean = S * (1.0f/512.0f);
        float var  = S2 * (1.0f/512.0f) - mean * mean;
        float inv  = rsqrtf(var + 1e-6f);
        size_t base = (size_t)(b * P1 + p0 + q) * DIM;
        #pragma unroll
        for (int j = 0; j < 4; j++)
            g_a1[base + t + j * 128] = __float2half_rn((y[j] - mean) * inv * lg[j] + lb[j]);
    }
}

// ---------------- GRN finalize + in-place fixup (slow path only); flag-guarded ----------------
__global__ void alpha_fix_kernel(int l, const float* __restrict__ grn_g,
                                 const float* __restrict__ grn_b) {
    if (!g_grnflag[l]) return;         // GRN trivial: A2 already = h, sumsq untouched (zero)
    int b = blockIdx.x;
    int i = threadIdx.x;               // 1024
    float gx = sqrtf(g_sumsq[b * INTER + i]);
    g_sumsq[b * INTER + i] = 0.0f;
    float r = gx;
    #pragma unroll
    for (int off = 16; off; off >>= 1) r += __shfl_xor_sync(0xffffffffu, r, off);
    __shared__ float sh[32];
    __shared__ float meansh;
    if ((i & 31) == 0) sh[i >> 5] = r;
    __syncthreads();
    if (i < 32) {
        float v = sh[i];
        #pragma unroll
        for (int off = 16; off; off >>= 1) v += __shfl_xor_sync(0xffffffffu, v, off);
        if (i == 0) meansh = v * (1.0f/1024.0f);
    }
    __syncthreads();
    float nx = gx / (meansh + 1e-6f);
    float alpha = grn_g[i] * nx + 1.0f;
    float gb = grn_b[i];
    __half* a2 = g_a2 + (size_t)(b * SEQ) * INTER + i;
    for (int p = 0; p < SEQ; p++) {
        float h = __half2float(a2[(size_t)p * INTER]);
        a2[(size_t)p * INTER] = __float2half_rn(alpha * h + gb);
    }
}

// ---------------- upsample: 8 rows per block ----------------
__global__ void upsample_kernel(const int* __restrict__ seq_len, float* __restrict__ out) {
    int blk = blockIdx.x;              // NB * 512
    int b  = blk >> 9;
    int p0 = (blk & 511) * 8;
    int al = seq_len[b];
    int base  = al >> 9;               // al/512 >= 2 (al >= 1024)
    int rem   = al & 511;
    int split = (512 - rem) * base;
    int t = threadIdx.x;               // 256
    int h = t >> 7;                    // half-block 0/1
    int c = t & 127;                   // float4 column
    #pragma unroll
    for (int qq = 0; qq < 4; qq++) {
        int p = p0 + h + qq * 2;
        float4* orow = (float4*)(out + (size_t)(b * MAXSEQ + p) * DIM);
        if (p >= al) { orow[c] = make_float4(0.f, 0.f, 0.f, 0.f); continue; }
        int j = (p < split) ? (p / base) : ((512 - rem) + (p - split) / (base + 1));
        if (j > 511) j = 511;
        orow[c] = ((const float4*)(g_x + (size_t)(b * SEQ + j) * DIM))[c];
    }
}

// ---------------- launch ----------------
extern "C" void kernel_launch(void* const* d_in, const int* in_sizes, int n_in,
                              void* d_out, int out_size) {
    const int*   text    = (const int*)  d_in[0];
    const int*   seq_len = (const int*)  d_in[1];
    const float* emb     = (const float*)d_in[2];
    const float* dw_w    = (const float*)d_in[3];
    const float* dw_b    = (const float*)d_in[4];
    const float* ln_g    = (const float*)d_in[5];
    const float* ln_b    = (const float*)d_in[6];
    const float* pw1_w   = (const float*)d_in[7];
    const float* pw1_b   = (const float*)d_in[8];
    const float* grn_g   = (const float*)d_in[9];
    const float* grn_b   = (const float*)d_in[10];
    const float* pw2_w   = (const float*)d_in[11];
    const float* pw2_b   = (const float*)d_in[12];
    float* out = (float*)d_out;

    static const int SMEM_BYTES = NSTAGE * (int)STAGE_BYTES;  // 96 KB
    cudaFuncSetAttribute(gemm1_mma, cudaFuncAttributeMaxDynamicSharedMemorySize, SMEM_BYTES);
    cudaFuncSetAttribute(gemm2_mma, cudaFuncAttributeMaxDynamicSharedMemorySize, SMEM_BYTES);

    prep_embed_kernel<<<NB * SEQ + 1024 * 2 * NLAYERS + NLAYERS, 256>>>(
        text, emb, pw1_w, pw2_w, grn_g, grn_b);
    for (int l = 0; l < NLAYERS; l++) {
        convln_kernel<<<NB * 129, 128>>>(dw_w + l * 7 * DIM, dw_b + l * DIM,
                                         ln_g + l * DIM, ln_b + l * DIM);
        gemm1_mma<<<dim3(INTER / 128, M1T), 128, SMEM_BYTES>>>(l, pw1_b + l * INTER);
        alpha_fix_kernel<<<NB, 1024>>>(l, grn_g + l * INTER, grn_b + l * INTER);
        gemm2_mma<<<dim3(DIM / 128, NB * SEQ / 128, 2), 128, SMEM_BYTES>>>(l, pw2_b + l * DIM);
    }
    upsample_kernel<<<NB * SEQ, 256>>>(seq_len, out);
}